// round 8
// baseline (speedup 1.0000x reference)
#include <cuda_runtime.h>
#include <math.h>

#define N_BOXES 256
#define N_VIEWS 6
#define P_TOT   (N_BOXES * N_VIEWS)   // 1536
#define C_FEAT  256
#define HF      116
#define WF      200
#define HW      (HF * WF)             // 23200
#define EPS     1e-8f

#define NBLK    148                   // one block per SM
#define NTHR    384                   // 12 warps
#define NWARP   12
#define FSCALE  4294967296.0          // 2^32 fixed-point scale
#define KBIG    0x7FFFFFFF

// Deterministic cross-block accumulators (integer atomics only)
__device__ unsigned long long g_sum  = 0ULL;
__device__ int                g_cnt  = 0;
__device__ int                g_done = 0;

// Project pair p; returns valid (0/1), writes packed clamped coords u0c | v0c<<8.
__device__ __forceinline__ int project_pair(int p,
                                            const float* __restrict__ boxes,
                                            const float* __restrict__ Kmat,
                                            const float* __restrict__ Tmat,
                                            const int*   __restrict__ img_sizes,
                                            int* coord_out)
{
    const int n = p / N_VIEWS;
    const int v = p - n * N_VIEWS;
    const float cx = boxes[n * 7 + 0];
    const float cy = boxes[n * 7 + 1];
    const float cz = boxes[n * 7 + 2];

    const float* Tv = Tmat + v * 16;   // 4x4 row-major
    const float pc0 = Tv[0] * cx + Tv[1] * cy + Tv[2]  * cz + Tv[3];
    const float pc1 = Tv[4] * cx + Tv[5] * cy + Tv[6]  * cz + Tv[7];
    const float pc2 = Tv[8] * cx + Tv[9] * cy + Tv[10] * cz + Tv[11];

    const float* Kv = Kmat + v * 9;    // 3x3 row-major
    const float q0 = Kv[0] * pc0 + Kv[1] * pc1 + Kv[2] * pc2;
    const float q1 = Kv[3] * pc0 + Kv[4] * pc1 + Kv[5] * pc2;
    const float q2 = Kv[6] * pc0 + Kv[7] * pc1 + Kv[8] * pc2;

    const float z  = pc2;
    const float u  = q0 / q2;          // ref: u = p2d.x / p2d.z
    const float vv = q1 / z;           // ref: v = p2d.y / p_cam.z

    const float Himg = (float)img_sizes[v * 2 + 0];
    const float Wimg = (float)img_sizes[v * 2 + 1];
    const int u0 = (int)floorf(u  * (float)WF / Wimg);
    const int v0 = (int)floorf(vv * (float)HF / Himg);

    const bool valid = (z > 0.0f) && (u >= 0.0f) && (u < Wimg) &&
                       (vv >= 0.0f) && (vv < Himg) &&
                       (u0 < WF - 1) && (v0 < HF - 1);

    const int u0c = min(max(u0, 0), WF - 2);
    const int v0c = min(max(v0, 0), HF - 2);
    *coord_out = u0c | (v0c << 8);
    return valid ? 1 : 0;
}

__global__ void __launch_bounds__(NTHR, 1)
fused_kernel(const float* __restrict__ boxes,
             const float* __restrict__ feats,
             const float* __restrict__ Kmat,
             const float* __restrict__ Tmat,
             const int*   __restrict__ img_sizes,
             float*       __restrict__ out)
{
    __shared__ int   s_key[NWARP];
    __shared__ int   s_pay[NWARP];
    __shared__ int   s_p0coord;
    __shared__ int   s_first;
    __shared__ int   s_fcoord;
    __shared__ float s_stored[C_FEAT];
    __shared__ float s_red[8];
    __shared__ float s_sinv;
    __shared__ float s_loss[NWARP];
    __shared__ int   s_lval[NWARP];

    const int tid  = threadIdx.x;
    const int warp = tid >> 5;
    const int lane = tid & 31;

    // ---- Step 0: own-pair projection + prefetch all gather loads into regs.
    // Clamped coords are always in-bounds, so loads are issued for every
    // p_own < P_TOT regardless of validity (results discarded if invalid).
    const int p_own = blockIdx.x + NBLK * warp;   // warps 0..10 may have a pair
    float y0[16], y1[16];
    int own_coord = 0, own_valid = 0;
    if (p_own < P_TOT) {
        own_valid = project_pair(p_own, boxes, Kmat, Tmat, img_sizes, &own_coord);
        const int u0   = own_coord & 0xFF;
        const int v0   = (own_coord >> 8) & 0xFF;
        const int view = p_own % N_VIEWS;
        const int du   = lane & 1;         // lanes 2j,2j+1 share a 128B line
        const int chof = lane >> 1;        // channel offset 0..15
        const float* base = feats + (size_t)view * C_FEAT * HW
                                  + (size_t)v0 * WF + u0 + du;
        #pragma unroll
        for (int i = 0; i < 16; i++) {
            const float* pch = base + (size_t)(chof + i * 16) * HW;
            y0[i] = pch[0];      // row v0
            y1[i] = pch[WF];     // row v0+1
        }
    } else {
        #pragma unroll
        for (int i = 0; i < 16; i++) { y0[i] = 0.0f; y1[i] = 0.0f; }
    }

    // ---- Step 1: block-wide sweep for first = min(p | valid), carrying the
    // winning pair's coords as payload. No atomics, no coord array.
    int bkey = KBIG, bpay = 0;
    #pragma unroll
    for (int i = 0; i < P_TOT / NTHR; i++) {
        const int p = tid + i * NTHR;
        int coord;
        const int valid = project_pair(p, boxes, Kmat, Tmat, img_sizes, &coord);
        if (p == 0 && tid == 0) s_p0coord = coord;   // fallback if none valid
        if (valid && p < bkey) { bkey = p; bpay = coord; }
    }
    #pragma unroll
    for (int o = 16; o > 0; o >>= 1) {
        const int k2 = __shfl_xor_sync(0xffffffffu, bkey, o);
        const int p2 = __shfl_xor_sync(0xffffffffu, bpay, o);
        if (k2 < bkey) { bkey = k2; bpay = p2; }
    }
    if (lane == 0) { s_key[warp] = bkey; s_pay[warp] = bpay; }
    __syncthreads();
    if (warp == 0) {
        int k  = (lane < NWARP) ? s_key[lane] : KBIG;
        int pp = (lane < NWARP) ? s_pay[lane] : 0;
        #pragma unroll
        for (int o = 8; o > 0; o >>= 1) {
            const int k2 = __shfl_xor_sync(0xffffffffu, k, o);
            const int p2 = __shfl_xor_sync(0xffffffffu, pp, o);
            if (k2 < k) { k = k2; pp = p2; }
        }
        if (lane == 0) {
            s_first  = (k == KBIG) ? 0 : k;
            s_fcoord = (k == KBIG) ? s_p0coord : pp;
        }
    }
    __syncthreads();
    const int first  = s_first;
    const int fcoord = s_fcoord;

    // ---- Step 2: gather 'stored' (first 256 threads, one channel each) ----
    if (tid < C_FEAT) {
        const int u0f   = fcoord & 0xFF;
        const int v0f   = (fcoord >> 8) & 0xFF;
        const int viewf = first % N_VIEWS;
        const float* pch = feats + (size_t)viewf * C_FEAT * HW
                                 + (size_t)tid * HW
                                 + (size_t)v0f * WF + u0f;
        const float fm = 0.25f * (pch[0] + pch[1] + pch[WF] + pch[WF + 1]);
        s_stored[tid] = fm;
        float sq = fm * fm;
        #pragma unroll
        for (int o = 16; o > 0; o >>= 1)
            sq += __shfl_xor_sync(0xffffffffu, sq, o);
        if (lane == 0) s_red[warp] = sq;     // warps 0..7
    }
    __syncthreads();
    if (tid == 0) {
        float t = 0.0f;
        #pragma unroll
        for (int k = 0; k < 8; k++) t += s_red[k];
        s_sinv = 1.0f / fmaxf(sqrtf(t), EPS);
    }
    __syncthreads();

    // ---- Step 3: finish own pair from prefetched registers ----
    {
        float loss = 0.0f;
        int   cnt  = 0;
        if (p_own < P_TOT && own_valid && p_own != first) {
            const int chof = lane >> 1;
            float s2[16];
            #pragma unroll
            for (int i = 0; i < 16; i++) s2[i] = y0[i] + y1[i];
            float dot = 0.0f, nrm = 0.0f;
            #pragma unroll
            for (int i = 0; i < 16; i++) {
                const float sp = __shfl_xor_sync(0xffffffffu, s2[i], 1);
                const float fm = 0.25f * (s2[i] + sp);
                dot += fm * s_stored[chof + i * 16];
                nrm += fm * fm;
            }
            #pragma unroll
            for (int o = 16; o > 0; o >>= 1) {
                dot += __shfl_xor_sync(0xffffffffu, dot, o);
                nrm += __shfl_xor_sync(0xffffffffu, nrm, o);
            }
            dot *= 0.5f;   // each channel counted by both du-lanes
            nrm *= 0.5f;
            const float inv_i = 1.0f / fmaxf(sqrtf(nrm), EPS);
            loss = 1.0f - dot * inv_i * s_sinv;
            cnt  = 1;
        }
        if (lane == 0) { s_loss[warp] = loss; s_lval[warp] = cnt; }
    }
    __syncthreads();

    // ---- Step 4: deterministic block sum -> fixed-point global atomics ----
    if (tid == 0) {
        float bsum = 0.0f;
        int   bcnt = 0;
        #pragma unroll
        for (int k = 0; k < NWARP; k++) { bsum += s_loss[k]; bcnt += s_lval[k]; }
        const long long q = llrint((double)bsum * FSCALE);
        atomicAdd(&g_sum, (unsigned long long)q);
        atomicAdd(&g_cnt, bcnt);
        __threadfence();
        const int done = atomicAdd(&g_done, 1);
        if (done == NBLK - 1) {
            const long long tot = (long long)atomicAdd(&g_sum, 0ULL);
            const int n = atomicAdd(&g_cnt, 0);
            out[0] = (n > 0) ? (float)(((double)tot / FSCALE) / (double)n) : 0.0f;
            // reset for next replay (kernel boundary orders this vs next launch)
            g_sum = 0ULL; g_cnt = 0; g_done = 0;
        }
    }
}

extern "C" void kernel_launch(void* const* d_in, const int* in_sizes, int n_in,
                              void* d_out, int out_size)
{
    const float* boxes     = (const float*)d_in[0];  // (256, 7)
    const float* feats     = (const float*)d_in[1];  // (6, 256, 116, 200)
    const float* Kmat      = (const float*)d_in[2];  // (6, 3, 3)
    const float* Tmat      = (const float*)d_in[3];  // (6, 4, 4)
    const int*   img_sizes = (const int*)d_in[4];    // (6, 2)
    float* out = (float*)d_out;

    fused_kernel<<<NBLK, NTHR>>>(boxes, feats, Kmat, Tmat, img_sizes, out);
}

// round 9
// speedup vs baseline: 1.1600x; 1.1600x over previous
#include <cuda_runtime.h>
#include <math.h>

#define N_BOXES 256
#define N_VIEWS 6
#define P_TOT   (N_BOXES * N_VIEWS)   // 1536
#define C_FEAT  256
#define HF      116
#define WF      200
#define HW      (HF * WF)             // 23200
#define EPS     1e-8f

#define NBLK    148                   // one block per SM
#define NTHR    384                   // 12 warps
#define NWARP   12
#define FSCALE  4294967296.0          // 2^32 fixed-point scale
#define KBIG    0x7FFFFFFF

// Deterministic cross-block accumulators (integer atomics only)
__device__ unsigned long long g_sum  = 0ULL;
__device__ int                g_cnt  = 0;
__device__ int                g_done = 0;

// Project pair p; returns valid (0/1), writes packed clamped coords u0c | v0c<<8.
__device__ __forceinline__ int project_pair(int p,
                                            const float* __restrict__ boxes,
                                            const float* __restrict__ Kmat,
                                            const float* __restrict__ Tmat,
                                            const int*   __restrict__ img_sizes,
                                            int* coord_out)
{
    const int n = p / N_VIEWS;
    const int v = p - n * N_VIEWS;
    const float cx = boxes[n * 7 + 0];
    const float cy = boxes[n * 7 + 1];
    const float cz = boxes[n * 7 + 2];

    const float* Tv = Tmat + v * 16;   // 4x4 row-major
    const float pc0 = Tv[0] * cx + Tv[1] * cy + Tv[2]  * cz + Tv[3];
    const float pc1 = Tv[4] * cx + Tv[5] * cy + Tv[6]  * cz + Tv[7];
    const float pc2 = Tv[8] * cx + Tv[9] * cy + Tv[10] * cz + Tv[11];

    const float* Kv = Kmat + v * 9;    // 3x3 row-major
    const float q0 = Kv[0] * pc0 + Kv[1] * pc1 + Kv[2] * pc2;
    const float q1 = Kv[3] * pc0 + Kv[4] * pc1 + Kv[5] * pc2;
    const float q2 = Kv[6] * pc0 + Kv[7] * pc1 + Kv[8] * pc2;

    const float z  = pc2;
    const float u  = q0 / q2;          // ref: u = p2d.x / p2d.z
    const float vv = q1 / z;           // ref: v = p2d.y / p_cam.z

    const float Himg = (float)img_sizes[v * 2 + 0];
    const float Wimg = (float)img_sizes[v * 2 + 1];
    const int u0 = (int)floorf(u  * (float)WF / Wimg);
    const int v0 = (int)floorf(vv * (float)HF / Himg);

    const bool valid = (z > 0.0f) && (u >= 0.0f) && (u < Wimg) &&
                       (vv >= 0.0f) && (vv < Himg) &&
                       (u0 < WF - 1) && (v0 < HF - 1);

    const int u0c = min(max(u0, 0), WF - 2);
    const int v0c = min(max(v0, 0), HF - 2);
    *coord_out = u0c | (v0c << 8);
    return valid ? 1 : 0;
}

__global__ void __launch_bounds__(NTHR, 1)
fused_kernel(const float* __restrict__ boxes,
             const float* __restrict__ feats,
             const float* __restrict__ Kmat,
             const float* __restrict__ Tmat,
             const int*   __restrict__ img_sizes,
             float*       __restrict__ out)
{
    __shared__ int   s_key[NWARP];
    __shared__ int   s_pay[NWARP];
    __shared__ int   s_p0coord;
    __shared__ int   s_first;
    __shared__ int   s_fcoord;
    __shared__ float s_stored[C_FEAT];
    __shared__ float s_red[8];
    __shared__ float s_sinv;
    __shared__ float s_loss[NWARP];
    __shared__ int   s_lval[NWARP];

    const int tid  = threadIdx.x;
    const int warp = tid >> 5;
    const int lane = tid & 31;

    // ---- Step 0: own-pair projection + prefetch gather loads into registers,
    // ONLY for valid pairs (invalid pairs contribute nothing; loading them
    // wastes L1tex wavefronts and L2 sectors — measured regression in R7).
    const int p_own = blockIdx.x + NBLK * warp;   // warps 0..10 may own a pair
    float y0[16], y1[16];
    int own_coord = 0, own_valid = 0;
    if (p_own < P_TOT)
        own_valid = project_pair(p_own, boxes, Kmat, Tmat, img_sizes, &own_coord);
    if (own_valid) {
        const int u0   = own_coord & 0xFF;
        const int v0   = (own_coord >> 8) & 0xFF;
        const int view = p_own % N_VIEWS;
        const int du   = lane & 1;         // lanes 2j,2j+1 share a 128B line
        const int chof = lane >> 1;        // channel offset 0..15
        const float* base = feats + (size_t)view * C_FEAT * HW
                                  + (size_t)v0 * WF + u0 + du;
        #pragma unroll
        for (int i = 0; i < 16; i++) {
            const float* pch = base + (size_t)(chof + i * 16) * HW;
            y0[i] = pch[0];      // row v0
            y1[i] = pch[WF];     // row v0+1
        }
    } else {
        #pragma unroll
        for (int i = 0; i < 16; i++) { y0[i] = 0.0f; y1[i] = 0.0f; }
    }

    // ---- Step 1: block-wide sweep for first = min(p | valid), carrying the
    // winning pair's coords as payload. No atomics, no coord array. Runs while
    // the prefetched loads are in flight.
    int bkey = KBIG, bpay = 0;
    #pragma unroll
    for (int i = 0; i < P_TOT / NTHR; i++) {
        const int p = tid + i * NTHR;
        int coord;
        const int valid = project_pair(p, boxes, Kmat, Tmat, img_sizes, &coord);
        if (p == 0 && tid == 0) s_p0coord = coord;   // fallback if none valid
        if (valid && p < bkey) { bkey = p; bpay = coord; }
    }
    #pragma unroll
    for (int o = 16; o > 0; o >>= 1) {
        const int k2 = __shfl_xor_sync(0xffffffffu, bkey, o);
        const int p2 = __shfl_xor_sync(0xffffffffu, bpay, o);
        if (k2 < bkey) { bkey = k2; bpay = p2; }
    }
    if (lane == 0) { s_key[warp] = bkey; s_pay[warp] = bpay; }
    __syncthreads();
    if (warp == 0) {
        int k  = (lane < NWARP) ? s_key[lane] : KBIG;
        int pp = (lane < NWARP) ? s_pay[lane] : 0;
        #pragma unroll
        for (int o = 8; o > 0; o >>= 1) {
            const int k2 = __shfl_xor_sync(0xffffffffu, k, o);
            const int p2 = __shfl_xor_sync(0xffffffffu, pp, o);
            if (k2 < k) { k = k2; pp = p2; }
        }
        if (lane == 0) {
            s_first  = (k == KBIG) ? 0 : k;
            s_fcoord = (k == KBIG) ? s_p0coord : pp;
        }
    }
    __syncthreads();
    const int first  = s_first;
    const int fcoord = s_fcoord;

    // ---- Step 2: gather 'stored' (first 256 threads, one channel each) ----
    if (tid < C_FEAT) {
        const int u0f   = fcoord & 0xFF;
        const int v0f   = (fcoord >> 8) & 0xFF;
        const int viewf = first % N_VIEWS;
        const float* pch = feats + (size_t)viewf * C_FEAT * HW
                                 + (size_t)tid * HW
                                 + (size_t)v0f * WF + u0f;
        const float fm = 0.25f * (pch[0] + pch[1] + pch[WF] + pch[WF + 1]);
        s_stored[tid] = fm;
        float sq = fm * fm;
        #pragma unroll
        for (int o = 16; o > 0; o >>= 1)
            sq += __shfl_xor_sync(0xffffffffu, sq, o);
        if (lane == 0) s_red[warp] = sq;     // warps 0..7
    }
    __syncthreads();
    if (tid == 0) {
        float t = 0.0f;
        #pragma unroll
        for (int k = 0; k < 8; k++) t += s_red[k];
        s_sinv = 1.0f / fmaxf(sqrtf(t), EPS);
    }
    __syncthreads();

    // ---- Step 3: finish own pair from prefetched registers ----
    {
        float loss = 0.0f;
        int   cnt  = 0;
        if (own_valid && p_own != first) {
            const int chof = lane >> 1;
            float s2[16];
            #pragma unroll
            for (int i = 0; i < 16; i++) s2[i] = y0[i] + y1[i];
            float dot = 0.0f, nrm = 0.0f;
            #pragma unroll
            for (int i = 0; i < 16; i++) {
                const float sp = __shfl_xor_sync(0xffffffffu, s2[i], 1);
                const float fm = 0.25f * (s2[i] + sp);
                dot += fm * s_stored[chof + i * 16];
                nrm += fm * fm;
            }
            #pragma unroll
            for (int o = 16; o > 0; o >>= 1) {
                dot += __shfl_xor_sync(0xffffffffu, dot, o);
                nrm += __shfl_xor_sync(0xffffffffu, nrm, o);
            }
            dot *= 0.5f;   // each channel counted by both du-lanes
            nrm *= 0.5f;
            const float inv_i = 1.0f / fmaxf(sqrtf(nrm), EPS);
            loss = 1.0f - dot * inv_i * s_sinv;
            cnt  = 1;
        }
        if (lane == 0) { s_loss[warp] = loss; s_lval[warp] = cnt; }
    }
    __syncthreads();

    // ---- Step 4: deterministic block sum -> fixed-point global atomics ----
    if (tid == 0) {
        float bsum = 0.0f;
        int   bcnt = 0;
        #pragma unroll
        for (int k = 0; k < NWARP; k++) { bsum += s_loss[k]; bcnt += s_lval[k]; }
        const long long q = llrint((double)bsum * FSCALE);
        atomicAdd(&g_sum, (unsigned long long)q);
        atomicAdd(&g_cnt, bcnt);
        __threadfence();
        const int done = atomicAdd(&g_done, 1);
        if (done == NBLK - 1) {
            const long long tot = (long long)atomicAdd(&g_sum, 0ULL);
            const int n = atomicAdd(&g_cnt, 0);
            out[0] = (n > 0) ? (float)(((double)tot / FSCALE) / (double)n) : 0.0f;
            // reset for next replay (kernel boundary orders this vs next launch)
            g_sum = 0ULL; g_cnt = 0; g_done = 0;
        }
    }
}

extern "C" void kernel_launch(void* const* d_in, const int* in_sizes, int n_in,
                              void* d_out, int out_size)
{
    const float* boxes     = (const float*)d_in[0];  // (256, 7)
    const float* feats     = (const float*)d_in[1];  // (6, 256, 116, 200)
    const float* Kmat      = (const float*)d_in[2];  // (6, 3, 3)
    const float* Tmat      = (const float*)d_in[3];  // (6, 4, 4)
    const int*   img_sizes = (const int*)d_in[4];    // (6, 2)
    float* out = (float*)d_out;

    fused_kernel<<<NBLK, NTHR>>>(boxes, feats, Kmat, Tmat, img_sizes, out);
}